// round 9
// baseline (speedup 1.0000x reference)
#include <cuda_runtime.h>
#include <math.h>

#define BS 32
#define NSAMP 64000
#define NTOT (BS*NSAMP)
#define TPB 128
#define BLK 16                 // XLA ReduceWindowRewriter base_length
#define NB1 (NSAMP/BLK)        // 4000 level-1 blocks per row
#define NB2 (NB1/BLK)          // 250 level-2 blocks
#define NB2P 256               // padded to multiple of 16
#define NB3 (NB2P/BLK)         // 16
#define HSTR 66                // smem h-row stride (even -> LDS.64 aligned)

__device__ float g_off1[BS*NB1]; // exclusive offset for each level-1 block

typedef unsigned long long u64;

__device__ __forceinline__ float ex2f(float x){ float r; asm("ex2.approx.f32 %0, %1;":"=f"(r):"f"(x)); return r; }
__device__ __forceinline__ float lg2f(float x){ float r; asm("lg2.approx.f32 %0, %1;":"=f"(r):"f"(x)); return r; }

// ---- packed f32x2 helpers ----
__device__ __forceinline__ u64 pack2(float lo, float hi){ u64 r; asm("mov.b64 %0, {%1,%2};":"=l"(r):"f"(lo),"f"(hi)); return r; }
__device__ __forceinline__ void unpack2(u64 v, float& lo, float& hi){ asm("mov.b64 {%0,%1}, %2;":"=f"(lo),"=f"(hi):"l"(v)); }
__device__ __forceinline__ u64 fma2(u64 a,u64 b,u64 c){ u64 r; asm("fma.rn.f32x2 %0,%1,%2,%3;":"=l"(r):"l"(a),"l"(b),"l"(c)); return r; }
__device__ __forceinline__ u64 mul2(u64 a,u64 b){ u64 r; asm("mul.rn.f32x2 %0,%1,%2;":"=l"(r):"l"(a),"l"(b)); return r; }
__device__ __forceinline__ u64 add2(u64 a,u64 b){ u64 r; asm("add.rn.f32x2 %0,%1,%2;":"=l"(r):"l"(a),"l"(b)); return r; }

// 2*sigmoid(x)^ln(10) + 1e-7
__device__ __forceinline__ float hfun(float x){
    float e = ex2f(-1.4426950408889634f * x);
    float u = lg2f(1.0f + e);
    return fmaf(2.0f, ex2f(-2.3025850929940457f * u), 1e-7f);
}

// increment: fast-math (arcp) form — multiply by compile-time-rounded reciprocal
__device__ __forceinline__ float incr(float f){
    const float RINV = 1.0f / 44100.0f;
    return __fmul_rn(__fmul_rn(6.283185307179586f, f), RINV);
}

// ---------------------------------------------------------------------------
// Fused scan kernel: one block per row. S1 -> (in-place) I2 -> I3 -> O4 -> off1
// ---------------------------------------------------------------------------
__global__ void __launch_bounds__(512) scan_kernel(const float* __restrict__ f0){
    __shared__ float sI2[NB1];
    __shared__ float sI3[NB2P];
    __shared__ float sO4[NB3];
    const int row = blockIdx.x, tid = threadIdx.x;
    const float* fr = f0 + (size_t)row * NSAMP;

    for (int j = tid; j < NB1; j += 512){
        const float4* fp = (const float4*)(fr + (size_t)j * BLK);
        float acc = 0.0f;
        #pragma unroll
        for (int i = 0; i < BLK/4; i++){
            float4 v = fp[i];
            float d0 = incr(v.x), d1 = incr(v.y), d2 = incr(v.z), d3 = incr(v.w);
            acc = (i == 0) ? d0 : __fadd_rn(acc, d0);
            acc = __fadd_rn(acc, d1);
            acc = __fadd_rn(acc, d2);
            acc = __fadd_rn(acc, d3);
        }
        sI2[j] = acc;
    }
    __syncthreads();

    if (tid < NB2){
        int b = tid * BLK;
        float acc = sI2[b];
        #pragma unroll
        for (int i = 1; i < BLK; i++){ acc = __fadd_rn(acc, sI2[b+i]); sI2[b+i] = acc; }
    }
    __syncthreads();

    if (tid < NB3){
        int b = tid * BLK;
        float acc = 0.0f;
        #pragma unroll
        for (int i = 0; i < BLK; i++){
            int m = b + i;
            float s2 = (m < NB2) ? sI2[m*BLK + (BLK-1)] : 0.0f;
            acc = (i == 0) ? s2 : __fadd_rn(acc, s2);
            sI3[m] = acc;
        }
    }
    __syncthreads();

    if (tid == 0){
        float acc = 0.0f;
        #pragma unroll
        for (int p = 0; p < NB3; p++){
            float s3 = sI3[p*BLK + (BLK-1)];
            acc = (p == 0) ? s3 : __fadd_rn(acc, s3);
            sO4[p] = acc;
        }
    }
    __syncthreads();

    float* off1 = g_off1 + row * NB1;
    for (int j = tid; j < NB1; j += 512){
        float v;
        if (j == 0) v = 0.0f;
        else {
            int jm = j - 1, q = jm >> 4;
            float o3e;
            if (q == 0) o3e = 0.0f;
            else {
                int qm = q - 1, p = qm >> 4;
                float o4e = (p == 0) ? 0.0f : sO4[p-1];
                o3e = __fadd_rn(o4e, sI3[qm]);
            }
            v = __fadd_rn(o3e, sI2[jm]);
        }
        off1[j] = v;
    }
}

// ---------------------------------------------------------------------------
// Oscillator: hfun applied during staging (h stored in smem, LDS.64 pairs);
// main loop is pure packed rotation + correction + accumulate.
// ---------------------------------------------------------------------------
__global__ void __launch_bounds__(TPB) osc_kernel(
    const float* __restrict__ f0,
    const float* __restrict__ amps,
    const float* __restrict__ phase,
    float* __restrict__ out)
{
    __shared__ float sH[TPB * HSTR];   // h[k] at sH[s*HSTR + (k-1)], k=1..64
    __shared__ float sTA[TPB];         // total_amplitude per sample
    __shared__ float sD[TPB];
    __shared__ float sOFF[TPB / BLK];
    const int tid    = threadIdx.x;
    const int nchunk = NSAMP / TPB;
    const int b      = blockIdx.x / nchunk;
    const int t0     = (blockIdx.x % nchunk) * TPB;
    const int sbase  = b * NSAMP + t0;

    // staging + hfun: coalesced scalar loads (adjacent threads -> adjacent floats),
    // 65 independent MUFU chains per thread hide under the LDG stream.
    {
        const float* gsrc = amps + (size_t)sbase * 65;
        #pragma unroll 5
        for (int i = tid; i < TPB * 65; i += TPB){
            int s = i / 65;
            int j = i - s * 65;
            float hv = hfun(gsrc[i]);
            if (j == 0) sTA[s] = hv;
            else        sH[s * HSTR + (j - 1)] = hv;
        }
    }
    const int idx   = sbase + tid;
    const float f0v = f0[idx];
    sD[tid] = incr(f0v);
    if (tid < TPB / BLK) sOFF[tid] = g_off1[(sbase >> 4) + tid];
    __syncthreads();

    // bit-exact omega/theta (within-16 ascending fold + one offset add)
    const int g = tid >> 4, i15 = tid & 15;
    float inc = sD[g * BLK];
    for (int i = 1; i <= i15; ++i) inc = __fadd_rn(inc, sD[g * BLK + i]);
    const float omega = __fadd_rn(sOFF[g], inc);
    const float theta = __fadd_rn(omega, phase[b]);

    // accurate sincos(theta): mod-pi in double
    const double thd = (double)theta;
    const double qd  = rint(thd * 0.31830988618379067154);
    const int    q   = (int)qd;
    const double rd  = fma(-3.14159265358979323846, qd, thd);
    const float  r   = (float)rd;
    const float  rl  = (float)(rd - (double)r);

    const float r2 = r * r;
    float p = -2.5052108385441718e-8f;
    p = fmaf(p, r2,  2.7557319223985893e-6f);
    p = fmaf(p, r2, -1.9841269841269841e-4f);
    p = fmaf(p, r2,  8.3333333333333333e-3f);
    p = fmaf(p, r2, -1.6666666666666667e-1f);
    const float sp = fmaf(r * r2, p, r);
    float qq = 2.0876756987868099e-9f;
    qq = fmaf(qq, r2, -2.7557319223985888e-7f);
    qq = fmaf(qq, r2,  2.4801587301587302e-5f);
    qq = fmaf(qq, r2, -1.3888888888888889e-3f);
    qq = fmaf(qq, r2,  4.1666666666666664e-2f);
    qq = fmaf(qq, r2, -0.5f);
    const float cp = fmaf(qq, r2, 1.0f);

    float s1 = fmaf(cp,  rl, sp);
    float c1 = fmaf(-sp, rl, cp);
    const float sg = (q & 1) ? -1.0f : 1.0f;
    s1 *= sg; c1 *= sg;

    const float s2v = 2.0f * s1 * c1;
    const float c2v = fmaf(-2.0f * s1, s1, 1.0f);

    // anti-alias cutoff: largest k with fl(f0*k) < 22050 (monotone in k).
    // f0 in [80,480) -> kc >= 45, so harmonics 1..44 are never masked.
    int kc = (int)(22050.0f / f0v);
    if (kc > 64) kc = 64;
    while (kc > 0  && __fmul_rn(f0v, (float)kc)     >= 22050.0f) --kc;
    while (kc < 64 && __fmul_rn(f0v, (float)(kc+1)) <  22050.0f) ++kc;

    const float* myH = sH + tid * HSTR;
    const float ta = sTA[tid];

    u64 S   = pack2(s1,  s2v);
    u64 C   = pack2(c1,  c2v);
    const u64 S2  = pack2(s2v,  s2v);
    const u64 C2  = pack2(c2v,  c2v);
    const u64 NS2 = pack2(-s2v, -s2v);
    const u64 TH  = pack2(theta,  theta);
    const u64 NTH = pack2(-theta, -theta);
    const u64 TWO = pack2(2.0f, 2.0f);
    u64 KF  = pack2(1.0f, 2.0f);
    u64 acc2 = pack2(0.0f, 0.0f);
    u64 sum2 = pack2(0.0f, 0.0f);

    // pairs j=0..21: k=1..44, never masked — LDS.64 gives the packed pair directly
    #pragma unroll
    for (int j = 0; j < 22; ++j){
        u64 h2 = *(const u64*)(myH + 2*j);
        sum2 = add2(sum2, h2);

        u64 a2  = mul2(TH, KF);
        u64 er2 = fma2(NTH, KF, a2);
        u64 sv2 = fma2(C, er2, S);      // sin(fl(k*theta)) ~= s + c*e
        acc2 = fma2(h2, sv2, acc2);

        u64 Sn = fma2(C, S2, mul2(S, C2));
        u64 Cn = fma2(S, NS2, mul2(C, C2));
        S = Sn; C = Cn;
        KF = add2(KF, TWO);
    }

    // pairs j=22..31: k=45..64, mask against kc
    #pragma unroll
    for (int j = 22; j < 32; ++j){
        const int kA = 2*j + 1;
        float hA, hB;
        unpack2(*(const u64*)(myH + 2*j), hA, hB);
        float mA = (kA     <= kc) ? hA : 0.0f;
        float mB = (kA + 1 <= kc) ? hB : 0.0f;
        u64 m2 = pack2(mA, mB);
        sum2 = add2(sum2, m2);

        u64 a2  = mul2(TH, KF);
        u64 er2 = fma2(NTH, KF, a2);
        u64 sv2 = fma2(C, er2, S);
        acc2 = fma2(m2, sv2, acc2);

        u64 Sn = fma2(C, S2, mul2(S, C2));
        u64 Cn = fma2(S, NS2, mul2(C, C2));
        S = Sn; C = Cn;
        KF = add2(KF, TWO);
    }

    float aA, aB, smA, smB;
    unpack2(acc2, aA, aB);
    unpack2(sum2, smA, smB);
    out[idx] = (aA + aB) * (ta / ((smA + smB) + 1e-5f));
}

extern "C" void kernel_launch(void* const* d_in, const int* in_sizes, int n_in,
                              void* d_out, int out_size)
{
    const float* f0    = (const float*)d_in[0];
    const float* amps  = (const float*)d_in[1];
    const float* phase = (const float*)d_in[2];
    float* out = (float*)d_out;

    scan_kernel<<<BS, 512>>>(f0);
    osc_kernel<<<(BS * NSAMP) / TPB, TPB>>>(f0, amps, phase, out);
}

// round 10
// speedup vs baseline: 1.5866x; 1.5866x over previous
#include <cuda_runtime.h>
#include <math.h>

#define BS 32
#define NSAMP 64000
#define NTOT (BS*NSAMP)
#define TPB 128
#define BLK 16                 // XLA ReduceWindowRewriter base_length
#define NB1 (NSAMP/BLK)        // 4000 level-1 blocks per row
#define NB2 (NB1/BLK)          // 250 level-2 blocks
#define NB2P 256               // padded to multiple of 16
#define NB3 (NB2P/BLK)         // 16

__device__ float g_off1[BS*NB1]; // exclusive offset for each level-1 block

typedef unsigned long long u64;

__device__ __forceinline__ float ex2f(float x){ float r; asm("ex2.approx.f32 %0, %1;":"=f"(r):"f"(x)); return r; }
__device__ __forceinline__ float lg2f(float x){ float r; asm("lg2.approx.f32 %0, %1;":"=f"(r):"f"(x)); return r; }

// ---- packed f32x2 helpers ----
__device__ __forceinline__ u64 pack2(float lo, float hi){ u64 r; asm("mov.b64 %0, {%1,%2};":"=l"(r):"f"(lo),"f"(hi)); return r; }
__device__ __forceinline__ void unpack2(u64 v, float& lo, float& hi){ asm("mov.b64 {%0,%1}, %2;":"=f"(lo),"=f"(hi):"l"(v)); }
__device__ __forceinline__ u64 fma2(u64 a,u64 b,u64 c){ u64 r; asm("fma.rn.f32x2 %0,%1,%2,%3;":"=l"(r):"l"(a),"l"(b),"l"(c)); return r; }
__device__ __forceinline__ u64 mul2(u64 a,u64 b){ u64 r; asm("mul.rn.f32x2 %0,%1,%2;":"=l"(r):"l"(a),"l"(b)); return r; }
__device__ __forceinline__ u64 add2(u64 a,u64 b){ u64 r; asm("add.rn.f32x2 %0,%1,%2;":"=l"(r):"l"(a),"l"(b)); return r; }

// 2*sigmoid(x)^ln(10) + 1e-7
__device__ __forceinline__ float hfun(float x){
    float e = ex2f(-1.4426950408889634f * x);
    float u = lg2f(1.0f + e);
    return fmaf(2.0f, ex2f(-2.3025850929940457f * u), 1e-7f);
}

// increment: fast-math (arcp) form — multiply by compile-time-rounded reciprocal
__device__ __forceinline__ float incr(float f){
    const float RINV = 1.0f / 44100.0f;
    return __fmul_rn(__fmul_rn(6.283185307179586f, f), RINV);
}

// ---------------------------------------------------------------------------
// Fused scan kernel: one block per row. S1 -> (in-place) I2 -> I3 -> O4 -> off1
// ---------------------------------------------------------------------------
__global__ void __launch_bounds__(512) scan_kernel(const float* __restrict__ f0){
    __shared__ float sI2[NB1];
    __shared__ float sI3[NB2P];
    __shared__ float sO4[NB3];
    const int row = blockIdx.x, tid = threadIdx.x;
    const float* fr = f0 + (size_t)row * NSAMP;

    for (int j = tid; j < NB1; j += 512){
        const float4* fp = (const float4*)(fr + (size_t)j * BLK);
        float acc = 0.0f;
        #pragma unroll
        for (int i = 0; i < BLK/4; i++){
            float4 v = fp[i];
            float d0 = incr(v.x), d1 = incr(v.y), d2 = incr(v.z), d3 = incr(v.w);
            acc = (i == 0) ? d0 : __fadd_rn(acc, d0);
            acc = __fadd_rn(acc, d1);
            acc = __fadd_rn(acc, d2);
            acc = __fadd_rn(acc, d3);
        }
        sI2[j] = acc;
    }
    __syncthreads();

    if (tid < NB2){
        int b = tid * BLK;
        float acc = sI2[b];
        #pragma unroll
        for (int i = 1; i < BLK; i++){ acc = __fadd_rn(acc, sI2[b+i]); sI2[b+i] = acc; }
    }
    __syncthreads();

    if (tid < NB3){
        int b = tid * BLK;
        float acc = 0.0f;
        #pragma unroll
        for (int i = 0; i < BLK; i++){
            int m = b + i;
            float s2 = (m < NB2) ? sI2[m*BLK + (BLK-1)] : 0.0f;
            acc = (i == 0) ? s2 : __fadd_rn(acc, s2);
            sI3[m] = acc;
        }
    }
    __syncthreads();

    if (tid == 0){
        float acc = 0.0f;
        #pragma unroll
        for (int p = 0; p < NB3; p++){
            float s3 = sI3[p*BLK + (BLK-1)];
            acc = (p == 0) ? s3 : __fadd_rn(acc, s3);
            sO4[p] = acc;
        }
    }
    __syncthreads();

    float* off1 = g_off1 + row * NB1;
    for (int j = tid; j < NB1; j += 512){
        float v;
        if (j == 0) v = 0.0f;
        else {
            int jm = j - 1, q = jm >> 4;
            float o3e;
            if (q == 0) o3e = 0.0f;
            else {
                int qm = q - 1, p = qm >> 4;
                float o4e = (p == 0) ? 0.0f : sO4[p-1];
                o3e = __fadd_rn(o4e, sI3[qm]);
            }
            v = __fadd_rn(o3e, sI2[jm]);
        }
        off1[j] = v;
    }
}

// ---------------------------------------------------------------------------
// Oscillator: hfun fused into float4 staging (linear index, no div/mod, deep
// MUFU ILP under the LDG stream). Main loop: pure packed rotation/accumulate.
// ---------------------------------------------------------------------------
__global__ void __launch_bounds__(TPB) osc_kernel(
    const float* __restrict__ f0,
    const float* __restrict__ amps,
    const float* __restrict__ phase,
    float* __restrict__ out)
{
    __shared__ float sH[TPB * 65];     // transformed amps, linear 65-stride
    __shared__ float sD[TPB];
    __shared__ float sOFF[TPB / BLK];
    const int tid    = threadIdx.x;
    const int nchunk = NSAMP / TPB;
    const int b      = blockIdx.x / nchunk;
    const int t0     = (blockIdx.x % nchunk) * TPB;
    const int sbase  = b * NSAMP + t0;

    {   // float4 staging with fused hfun: 2080 float4s per block
        const float4* gsrc = (const float4*)(amps + (size_t)sbase * 65);
        float4* sdst = (float4*)sH;
        #pragma unroll 4
        for (int i = tid; i < TPB * 65 / 4; i += TPB){
            float4 v = gsrc[i];
            v.x = hfun(v.x); v.y = hfun(v.y); v.z = hfun(v.z); v.w = hfun(v.w);
            sdst[i] = v;
        }
    }
    const int idx   = sbase + tid;
    const float f0v = f0[idx];
    sD[tid] = incr(f0v);
    if (tid < TPB / BLK) sOFF[tid] = g_off1[(sbase >> 4) + tid];
    __syncthreads();

    // bit-exact omega/theta (within-16 ascending fold + one offset add)
    const int g = tid >> 4, i15 = tid & 15;
    float inc = sD[g * BLK];
    for (int i = 1; i <= i15; ++i) inc = __fadd_rn(inc, sD[g * BLK + i]);
    const float omega = __fadd_rn(sOFF[g], inc);
    const float theta = __fadd_rn(omega, phase[b]);

    // accurate sincos(theta): mod-pi in double
    const double thd = (double)theta;
    const double qd  = rint(thd * 0.31830988618379067154);
    const int    q   = (int)qd;
    const double rd  = fma(-3.14159265358979323846, qd, thd);
    const float  r   = (float)rd;
    const float  rl  = (float)(rd - (double)r);

    const float r2 = r * r;
    float p = -2.5052108385441718e-8f;
    p = fmaf(p, r2,  2.7557319223985893e-6f);
    p = fmaf(p, r2, -1.9841269841269841e-4f);
    p = fmaf(p, r2,  8.3333333333333333e-3f);
    p = fmaf(p, r2, -1.6666666666666667e-1f);
    const float sp = fmaf(r * r2, p, r);
    float qq = 2.0876756987868099e-9f;
    qq = fmaf(qq, r2, -2.7557319223985888e-7f);
    qq = fmaf(qq, r2,  2.4801587301587302e-5f);
    qq = fmaf(qq, r2, -1.3888888888888889e-3f);
    qq = fmaf(qq, r2,  4.1666666666666664e-2f);
    qq = fmaf(qq, r2, -0.5f);
    const float cp = fmaf(qq, r2, 1.0f);

    float s1 = fmaf(cp,  rl, sp);
    float c1 = fmaf(-sp, rl, cp);
    const float sg = (q & 1) ? -1.0f : 1.0f;
    s1 *= sg; c1 *= sg;

    const float s2v = 2.0f * s1 * c1;
    const float c2v = fmaf(-2.0f * s1, s1, 1.0f);

    // anti-alias cutoff: largest k with fl(f0*k) < 22050 (monotone in k).
    // f0 in [80,480) -> kc >= 45, so harmonics 1..44 are never masked.
    int kc = (int)(22050.0f / f0v);
    if (kc > 64) kc = 64;
    while (kc > 0  && __fmul_rn(f0v, (float)kc)     >= 22050.0f) --kc;
    while (kc < 64 && __fmul_rn(f0v, (float)(kc+1)) <  22050.0f) ++kc;

    const float* my = sH + tid * 65;   // my[0]=total_amp, my[k]=h(k)
    const float ta = my[0];

    u64 S   = pack2(s1,  s2v);
    u64 C   = pack2(c1,  c2v);
    const u64 S2  = pack2(s2v,  s2v);
    const u64 C2  = pack2(c2v,  c2v);
    const u64 NS2 = pack2(-s2v, -s2v);
    const u64 TH  = pack2(theta,  theta);
    const u64 NTH = pack2(-theta, -theta);
    const u64 TWO = pack2(2.0f, 2.0f);
    u64 KF  = pack2(1.0f, 2.0f);
    u64 acc2 = pack2(0.0f, 0.0f);
    u64 sum2 = pack2(0.0f, 0.0f);

    // pairs j=0..21: k=1..44, never masked
    #pragma unroll
    for (int j = 0; j < 22; ++j){
        u64 h2 = pack2(my[2*j + 1], my[2*j + 2]);
        sum2 = add2(sum2, h2);

        u64 a2  = mul2(TH, KF);
        u64 er2 = fma2(NTH, KF, a2);
        u64 sv2 = fma2(C, er2, S);      // sin(fl(k*theta)) ~= s + c*e
        acc2 = fma2(h2, sv2, acc2);

        u64 Sn = fma2(C, S2, mul2(S, C2));
        u64 Cn = fma2(S, NS2, mul2(C, C2));
        S = Sn; C = Cn;
        KF = add2(KF, TWO);
    }

    // pairs j=22..31: k=45..64, masked against kc
    #pragma unroll
    for (int j = 22; j < 32; ++j){
        const int kA = 2*j + 1;
        float hA = my[kA], hB = my[kA + 1];
        float mA = (kA     <= kc) ? hA : 0.0f;
        float mB = (kA + 1 <= kc) ? hB : 0.0f;
        u64 m2 = pack2(mA, mB);
        sum2 = add2(sum2, m2);

        u64 a2  = mul2(TH, KF);
        u64 er2 = fma2(NTH, KF, a2);
        u64 sv2 = fma2(C, er2, S);
        acc2 = fma2(m2, sv2, acc2);

        u64 Sn = fma2(C, S2, mul2(S, C2));
        u64 Cn = fma2(S, NS2, mul2(C, C2));
        S = Sn; C = Cn;
        KF = add2(KF, TWO);
    }

    float aA, aB, smA, smB;
    unpack2(acc2, aA, aB);
    unpack2(sum2, smA, smB);
    out[idx] = (aA + aB) * (ta / ((smA + smB) + 1e-5f));
}

extern "C" void kernel_launch(void* const* d_in, const int* in_sizes, int n_in,
                              void* d_out, int out_size)
{
    const float* f0    = (const float*)d_in[0];
    const float* amps  = (const float*)d_in[1];
    const float* phase = (const float*)d_in[2];
    float* out = (float*)d_out;

    scan_kernel<<<BS, 512>>>(f0);
    osc_kernel<<<(BS * NSAMP) / TPB, TPB>>>(f0, amps, phase, out);
}